// round 15
// baseline (speedup 1.0000x reference)
#include <cuda_runtime.h>
#include <cstdint>
#include <math.h>

#define V 50257
#define H 1024
#define L 128
#define NLOGIT_BLOCKS ((V + 15) / 16)   // 3142

// ---------------- scratch (device globals) ----------------
__device__ float g_attn_logits[L];
__device__ float g_attn_applied[H];
__device__ float g_x[H];
__device__ float g_gi0[3 * H];
__device__ float g_gh0[3 * H];
__device__ float g_gi1[3 * H];
__device__ float g_gh1[3 * H];
__device__ float g_h0[H];
__device__ float g_h1[H];
__device__ float g_red_max[NLOGIT_BLOCKS];
__device__ float g_red_sum[NLOGIT_BLOCKS];

// ---------------- helpers ----------------
__inline__ __device__ float warpReduceSum(float v) {
    #pragma unroll
    for (int o = 16; o > 0; o >>= 1) v += __shfl_down_sync(0xffffffffu, v, o);
    return v;
}
__inline__ __device__ float warpReduceMax(float v) {
    #pragma unroll
    for (int o = 16; o > 0; o >>= 1) v = fmaxf(v, __shfl_down_sync(0xffffffffu, v, o));
    return v;
}
__inline__ __device__ float blockReduceSum(float v, float* sh) {
    int lane = threadIdx.x & 31, wid = threadIdx.x >> 5;
    v = warpReduceSum(v);
    if (lane == 0) sh[wid] = v;
    __syncthreads();
    int nw = blockDim.x >> 5;
    v = (threadIdx.x < nw) ? sh[lane] : 0.f;
    if (wid == 0) v = warpReduceSum(v);
    return v;
}
__inline__ __device__ float blockReduceMax(float v, float* sh) {
    int lane = threadIdx.x & 31, wid = threadIdx.x >> 5;
    v = warpReduceMax(v);
    if (lane == 0) sh[wid] = v;
    __syncthreads();
    int nw = blockDim.x >> 5;
    v = (threadIdx.x < nw) ? sh[lane] : -INFINITY;
    if (wid == 0) v = warpReduceMax(v);
    return v;
}
__inline__ __device__ float dot4(float4 a, float4 b) {
    return a.x * b.x + a.y * b.y + a.z * b.z + a.w * b.w;
}
// end-of-kernel trigger: all writes ordered before (post-syncthreads)
__inline__ __device__ void trigger_done() {
    __syncthreads();
    cudaTriggerProgrammaticLaunchCompletion();
}

// ---------------- TMA bulk copy + mbarrier helpers ----------------
__inline__ __device__ void mbar_init(unsigned mbar) {
    asm volatile("mbarrier.init.shared.b64 [%0], 1;" :: "r"(mbar) : "memory");
}
__inline__ __device__ void mbar_expect_tx(unsigned mbar, unsigned bytes) {
    asm volatile("mbarrier.arrive.expect_tx.shared.b64 _, [%0], %1;"
                 :: "r"(mbar), "r"(bytes) : "memory");
}
__inline__ __device__ void bulk_g2s(unsigned dst, const void* src, unsigned bytes,
                                    unsigned mbar) {
    asm volatile(
        "cp.async.bulk.shared::cta.global.mbarrier::complete_tx::bytes [%0], [%1], %2, [%3];"
        :: "r"(dst), "l"(src), "r"(bytes), "r"(mbar) : "memory");
}
__inline__ __device__ void mbar_wait0(unsigned mbar) {
    asm volatile(
        "{\n\t"
        ".reg .pred P1;\n\t"
        "WAIT_LOOP_%=:\n\t"
        "mbarrier.try_wait.parity.acquire.cta.shared::cta.b64 P1, [%0], 0, 0x989680;\n\t"
        "@P1 bra.uni WAIT_DONE_%=;\n\t"
        "bra.uni WAIT_LOOP_%=;\n\t"
        "WAIT_DONE_%=:\n\t"
        "}"
        :: "r"(mbar) : "memory");
}

// ---------------- K1: fused attn_logits + gh0 + gh1 -------------------------
__global__ void __launch_bounds__(256) k_phase1(
        const long long* __restrict__ ids,
        const float* __restrict__ emb,
        const float* __restrict__ hidden,
        const float* __restrict__ attn_w,
        const float* __restrict__ attn_b,
        const float* __restrict__ w_hh0,
        const float* __restrict__ b_hh0,
        const float* __restrict__ w_hh1,
        const float* __restrict__ b_hh1) {
    __shared__ alignas(128) float4 sw[2048];   // 32KB
    __shared__ alignas(8) unsigned long long mbar_s;
    __shared__ float shpart[8];
    int t = threadIdx.x, warp = t >> 5, lane = t & 31;
    unsigned mbar = (unsigned)__cvta_generic_to_shared(&mbar_s);
    unsigned sdst = (unsigned)__cvta_generic_to_shared(sw);
    int b = blockIdx.x;

    if (t == 0) mbar_init(mbar);
    __syncthreads();

    if (b < 32) {
        int row0 = b * 4;  // 4 rows of width 2048
        if (t == 0) {
            mbar_expect_tx(mbar, 32768);
            bulk_g2s(sdst, attn_w + (size_t)row0 * (2 * H), 32768, mbar);
        }
        const float4* src = (warp & 1) ? (const float4*)hidden
                                       : (const float4*)(emb + (size_t)ids[0] * H);
        float4 xv[8];
        #pragma unroll
        for (int i = 0; i < 8; i++) xv[i] = __ldg(&src[lane + 32 * i]);
        mbar_wait0(mbar);
        float s = 0.f;
        #pragma unroll
        for (int i = 0; i < 8; i++) s += dot4(sw[warp * 256 + lane + 32 * i], xv[i]);
        s = warpReduceSum(s);
        if (lane == 0) shpart[warp] = s;
        __syncthreads();
        if (t < 4) g_attn_logits[row0 + t] = shpart[2 * t] + shpart[2 * t + 1] + attn_b[row0 + t];
    } else {
        bool is0 = (b < 32 + 384);
        int row0 = (is0 ? (b - 32) : (b - 416)) * 8;
        const float* wmat = is0 ? w_hh0 : w_hh1;
        const float* bias = is0 ? b_hh0 : b_hh1;
        const float4* hv4 = (const float4*)(is0 ? hidden : hidden + H);
        float* dst = is0 ? g_gh0 : g_gh1;
        if (t == 0) {
            mbar_expect_tx(mbar, 32768);
            bulk_g2s(sdst, wmat + (size_t)row0 * H, 32768, mbar);
        }
        float4 xv[8];
        #pragma unroll
        for (int i = 0; i < 8; i++) xv[i] = __ldg(&hv4[lane + 32 * i]);
        mbar_wait0(mbar);
        float s = 0.f;
        #pragma unroll
        for (int i = 0; i < 8; i++) s += dot4(sw[warp * 256 + lane + 32 * i], xv[i]);
        s = warpReduceSum(s);
        int row = row0 + warp;
        if (lane == 0) dst[row] = s + bias[row];
    }
    trigger_done();
}

// ---------------- K2: softmax (redundant per block) + attn_applied ----------
__global__ void k_softmax_applied(const float* __restrict__ enc,
                                  float* __restrict__ out) {
    cudaGridDependencySynchronize();
    __shared__ float sh[32];
    __shared__ float sM, sS;
    __shared__ float aw[L];
    int t = threadIdx.x;  // 128
    float v = g_attn_logits[t];
    float m = blockReduceMax(v, sh);
    if (t == 0) sM = m;
    __syncthreads();
    float e = expf(v - sM);
    __syncthreads();
    float s = blockReduceSum(e, sh);
    if (t == 0) sS = s;
    __syncthreads();
    float w = e / sS;
    aw[t] = w;
    if (blockIdx.x == 0) out[V + 2 * H + t] = w;
    __syncthreads();
    int h = blockIdx.x * 128 + t;
    float acc = 0.f;
    #pragma unroll 8
    for (int l = 0; l < L; l++) acc += aw[l] * enc[(size_t)l * H + h];
    g_attn_applied[h] = acc;
    trigger_done();
}

// ---------------- K3: comb + relu (4 rows x 2048 per block) ------------------
__global__ void __launch_bounds__(256) k_comb(
        const long long* __restrict__ ids,
        const float* __restrict__ emb,
        const float* __restrict__ comb_w,
        const float* __restrict__ comb_b) {
    __shared__ alignas(128) float4 sw[2048];
    __shared__ alignas(8) unsigned long long mbar_s;
    __shared__ float shpart[8];
    int t = threadIdx.x, warp = t >> 5, lane = t & 31;
    unsigned mbar = (unsigned)__cvta_generic_to_shared(&mbar_s);
    unsigned sdst = (unsigned)__cvta_generic_to_shared(sw);
    int row0 = blockIdx.x * 4;

    if (t == 0) mbar_init(mbar);
    __syncthreads();
    if (t == 0) {
        mbar_expect_tx(mbar, 32768);
        bulk_g2s(sdst, comb_w + (size_t)row0 * (2 * H), 32768, mbar);  // weights: no dep
    }
    cudaGridDependencySynchronize();   // wait for attn_applied
    const float4* src = (warp & 1) ? (const float4*)g_attn_applied
                                   : (const float4*)(emb + (size_t)ids[0] * H);
    float4 xv[8];
    #pragma unroll
    for (int i = 0; i < 8; i++) xv[i] = __ldg(&src[lane + 32 * i]);
    mbar_wait0(mbar);
    float s = 0.f;
    #pragma unroll
    for (int i = 0; i < 8; i++) s += dot4(sw[warp * 256 + lane + 32 * i], xv[i]);
    s = warpReduceSum(s);
    if (lane == 0) shpart[warp] = s;
    __syncthreads();
    if (t < 4) {
        float r = shpart[2 * t] + shpart[2 * t + 1] + comb_b[row0 + t];
        g_x[row0 + t] = r > 0.f ? r : 0.f;
    }
    trigger_done();
}

// ---------------- K4/K6: gi = x @ w_ih^T + b_ih (8 rows x 1024) --------------
__global__ void __launch_bounds__(256) k_gi(
        const float* __restrict__ xin,
        const float* __restrict__ w_ih,
        const float* __restrict__ b_ih,
        float* __restrict__ gi) {
    __shared__ alignas(128) float4 sw[2048];
    __shared__ alignas(8) unsigned long long mbar_s;
    int t = threadIdx.x, warp = t >> 5, lane = t & 31;
    unsigned mbar = (unsigned)__cvta_generic_to_shared(&mbar_s);
    unsigned sdst = (unsigned)__cvta_generic_to_shared(sw);
    int row0 = blockIdx.x * 8;

    if (t == 0) mbar_init(mbar);
    __syncthreads();
    if (t == 0) {
        mbar_expect_tx(mbar, 32768);
        bulk_g2s(sdst, w_ih + (size_t)row0 * H, 32768, mbar);   // weights: no dep
    }
    cudaGridDependencySynchronize();   // wait for x / h0
    const float4* x4 = (const float4*)xin;
    float4 xv[8];
    #pragma unroll
    for (int i = 0; i < 8; i++) xv[i] = __ldg(&x4[lane + 32 * i]);
    mbar_wait0(mbar);
    float s = 0.f;
    #pragma unroll
    for (int i = 0; i < 8; i++) s += dot4(sw[warp * 256 + lane + 32 * i], xv[i]);
    s = warpReduceSum(s);
    int row = row0 + warp;
    if (lane == 0) gi[row] = s + b_ih[row];
    trigger_done();
}

// ---------------- K5/K7: GRU combine ------------------------------------------
__global__ void k_combine(const float* __restrict__ gi,
                          const float* __restrict__ gh,
                          const float* __restrict__ hprev,
                          float* __restrict__ hnew,
                          float* __restrict__ out_hid) {
    cudaGridDependencySynchronize();
    int t = threadIdx.x;
    float r = 1.f / (1.f + expf(-(gi[t] + gh[t])));
    float z = 1.f / (1.f + expf(-(gi[H + t] + gh[H + t])));
    float n = tanhf(gi[2 * H + t] + r * gh[2 * H + t]);
    float h = (1.f - z) * n + z * hprev[t];
    hnew[t] = h;
    out_hid[t] = h;
    trigger_done();
}

// ---------------- K8: logits + fused per-block lse partials -------------------
__global__ void __launch_bounds__(256) k_logits(
        const float* __restrict__ out_w,
        const float* __restrict__ out_b,
        float* __restrict__ logits) {
    __shared__ float sv[16];
    int warp = threadIdx.x >> 5;
    int lane = threadIdx.x & 31;
    if (threadIdx.x < 16) sv[threadIdx.x] = -INFINITY;
    int j0 = (blockIdx.x * 8 + warp) * 2;

    if (j0 < V) {
        const float4* w0 = (const float4*)(out_w + (size_t)j0 * H);
        bool has1 = (j0 + 1) < V;
        const float4* w1 = (const float4*)(out_w + (size_t)(has1 ? j0 + 1 : j0) * H);

        // weight loads depend only on external input — start before the dependency sync
        float4 w0v[8], w1v[8];
        #pragma unroll
        for (int i = 0; i < 8; i++) w0v[i] = __ldcs(&w0[lane + 32 * i]);
        #pragma unroll
        for (int i = 0; i < 8; i++) w1v[i] = __ldcs(&w1[lane + 32 * i]);

        cudaGridDependencySynchronize();   // wait for h1

        const float4* h = (const float4*)g_h1;
        float4 hv[8];
        #pragma unroll
        for (int i = 0; i < 8; i++) hv[i] = __ldg(&h[lane + 32 * i]);

        float s0 = 0.f, s1 = 0.f;
        #pragma unroll
        for (int i = 0; i < 8; i++) {
            s0 += dot4(w0v[i], hv[i]);
            s1 += dot4(w1v[i], hv[i]);
        }
        s0 = warpReduceSum(s0);
        s1 = warpReduceSum(s1);
        if (lane == 0) {
            float l0 = s0 + out_b[j0];
            logits[j0] = l0;
            sv[warp * 2] = l0;
            if (has1) {
                float l1 = s1 + out_b[j0 + 1];
                logits[j0 + 1] = l1;
                sv[warp * 2 + 1] = l1;
            }
        }
    } else {
        cudaGridDependencySynchronize();
    }
    __syncthreads();
    if (threadIdx.x == 0) {
        float m = -INFINITY;
        #pragma unroll
        for (int i = 0; i < 16; i++) m = fmaxf(m, sv[i]);
        float s = 0.f;
        #pragma unroll
        for (int i = 0; i < 16; i++)
            if (sv[i] > -INFINITY) s += expf(sv[i] - m);
        g_red_max[blockIdx.x] = m;
        g_red_sum[blockIdx.x] = s;
    }
    trigger_done();
}

// ---------------- K9: reduce partials (redundant per block) + apply -----------
__global__ void k_lse_apply(float* __restrict__ logits) {
    cudaGridDependencySynchronize();
    __shared__ float sh[32];
    __shared__ float sM, sLogZ;
    int t = threadIdx.x;
    float m = -INFINITY;
    for (int i = t; i < NLOGIT_BLOCKS; i += 256) m = fmaxf(m, g_red_max[i]);
    float M = blockReduceMax(m, sh);
    if (t == 0) sM = M;
    __syncthreads();
    M = sM;
    float s = 0.f;
    for (int i = t; i < NLOGIT_BLOCKS; i += 256)
        s += g_red_sum[i] * expf(g_red_max[i] - M);
    __syncthreads();
    s = blockReduceSum(s, sh);
    if (t == 0) sLogZ = M + logf(s);
    __syncthreads();
    float lz = sLogZ;
    int base = blockIdx.x * 1024 + t;
    #pragma unroll
    for (int k = 0; k < 4; k++) {
        int i = base + k * 256;
        if (i < V) logits[i] -= lz;
    }
}

// =================================================================================
template <typename... Args>
static void launch_pdl(void (*kern)(Args...), dim3 grid, dim3 block, Args... args) {
    cudaLaunchConfig_t cfg = {};
    cfg.gridDim = grid;
    cfg.blockDim = block;
    cfg.dynamicSmemBytes = 0;
    cfg.stream = 0;
    cudaLaunchAttribute attr[1];
    attr[0].id = cudaLaunchAttributeProgrammaticStreamSerialization;
    attr[0].val.programmaticStreamSerializationAllowed = 1;
    cfg.attrs = attr;
    cfg.numAttrs = 1;
    cudaLaunchKernelEx(&cfg, kern, args...);
}

extern "C" void kernel_launch(void* const* d_in, const int* in_sizes, int n_in,
                              void* d_out, int out_size) {
    const long long* input_ids = (const long long*)d_in[0];
    const float* hidden  = (const float*)d_in[1];
    const float* enc     = (const float*)d_in[2];
    const float* emb     = (const float*)d_in[3];
    const float* attn_w  = (const float*)d_in[4];
    const float* attn_b  = (const float*)d_in[5];
    const float* comb_w  = (const float*)d_in[6];
    const float* comb_b  = (const float*)d_in[7];
    const float* w_ih0   = (const float*)d_in[8];
    const float* w_hh0   = (const float*)d_in[9];
    const float* b_ih0   = (const float*)d_in[10];
    const float* b_hh0   = (const float*)d_in[11];
    const float* w_ih1   = (const float*)d_in[12];
    const float* w_hh1   = (const float*)d_in[13];
    const float* b_ih1   = (const float*)d_in[14];
    const float* b_hh1   = (const float*)d_in[15];
    const float* out_w   = (const float*)d_in[16];
    const float* out_b   = (const float*)d_in[17];

    float* out = (float*)d_out;

    const float* h0_prev = hidden;
    const float* h1_prev = hidden + H;

    float* p_x;   cudaGetSymbolAddress((void**)&p_x, g_x);
    float* p_h0;  cudaGetSymbolAddress((void**)&p_h0, g_h0);
    float* p_h1;  cudaGetSymbolAddress((void**)&p_h1, g_h1);
    float* p_gi0; cudaGetSymbolAddress((void**)&p_gi0, g_gi0);
    float* p_gh0; cudaGetSymbolAddress((void**)&p_gh0, g_gh0);
    float* p_gi1; cudaGetSymbolAddress((void**)&p_gi1, g_gi1);
    float* p_gh1; cudaGetSymbolAddress((void**)&p_gh1, g_gh1);

    // Phase 1 (first node: plain launch)
    k_phase1<<<32 + 2 * 384, 256>>>(input_ids, emb, hidden, attn_w, attn_b,
                                    w_hh0, b_hh0, w_hh1, b_hh1);
    // All successors: PDL — launch early; predecessors trigger only after writes
    launch_pdl(k_softmax_applied, dim3(8), dim3(128), enc, out);
    launch_pdl(k_comb, dim3(H / 4), dim3(256), input_ids, emb, comb_w, comb_b);
    launch_pdl(k_gi, dim3(3 * H / 8), dim3(256),
               (const float*)p_x, w_ih0, b_ih0, p_gi0);
    launch_pdl(k_combine, dim3(1), dim3(H),
               (const float*)p_gi0, (const float*)p_gh0, h0_prev, p_h0, out + V);
    launch_pdl(k_gi, dim3(3 * H / 8), dim3(256),
               (const float*)p_h0, w_ih1, b_ih1, p_gi1);
    launch_pdl(k_combine, dim3(1), dim3(H),
               (const float*)p_gi1, (const float*)p_gh1, h1_prev, p_h1, out + V + H);
    launch_pdl(k_logits, dim3(NLOGIT_BLOCKS), dim3(256), out_w, out_b, out);
    launch_pdl(k_lse_apply, dim3((V + 1023) / 1024), dim3(256), out);
}

// round 16
// speedup vs baseline: 1.1508x; 1.1508x over previous
#include <cuda_runtime.h>
#include <cstdint>
#include <math.h>

#define V 50257
#define H 1024
#define L 128
#define RED_BLOCKS 128

// ---------------- scratch (device globals) ----------------
__device__ float g_attn_logits[L];
__device__ float g_attn_applied[H];
__device__ float g_x[H];
__device__ float g_gi0[3 * H];
__device__ float g_gh0[3 * H];
__device__ float g_gi1[3 * H];
__device__ float g_gh1[3 * H];
__device__ float g_h0[H];
__device__ float g_h1[H];
__device__ float g_red_max[RED_BLOCKS];
__device__ float g_red_sum[RED_BLOCKS];
__device__ unsigned g_lse_ctr;    // zero-init; self-resetting each run
__device__ unsigned g_lse_epoch;  // monotonic across graph replays

// ---------------- helpers ----------------
__inline__ __device__ float warpReduceSum(float v) {
    #pragma unroll
    for (int o = 16; o > 0; o >>= 1) v += __shfl_down_sync(0xffffffffu, v, o);
    return v;
}
__inline__ __device__ float warpReduceMax(float v) {
    #pragma unroll
    for (int o = 16; o > 0; o >>= 1) v = fmaxf(v, __shfl_down_sync(0xffffffffu, v, o));
    return v;
}
__inline__ __device__ float blockReduceSum(float v, float* sh) {
    int lane = threadIdx.x & 31, wid = threadIdx.x >> 5;
    v = warpReduceSum(v);
    if (lane == 0) sh[wid] = v;
    __syncthreads();
    int nw = blockDim.x >> 5;
    v = (threadIdx.x < nw) ? sh[lane] : 0.f;
    if (wid == 0) v = warpReduceSum(v);
    return v;
}
__inline__ __device__ float blockReduceMax(float v, float* sh) {
    int lane = threadIdx.x & 31, wid = threadIdx.x >> 5;
    v = warpReduceMax(v);
    if (lane == 0) sh[wid] = v;
    __syncthreads();
    int nw = blockDim.x >> 5;
    v = (threadIdx.x < nw) ? sh[lane] : -INFINITY;
    if (wid == 0) v = warpReduceMax(v);
    return v;
}
__inline__ __device__ float dot4(float4 a, float4 b) {
    return a.x * b.x + a.y * b.y + a.z * b.z + a.w * b.w;
}
// end-of-kernel trigger: all writes ordered before (post-syncthreads)
__inline__ __device__ void trigger_done() {
    __syncthreads();
    cudaTriggerProgrammaticLaunchCompletion();
}

// ---------------- TMA bulk copy + mbarrier helpers ----------------
__inline__ __device__ void mbar_init(unsigned mbar) {
    asm volatile("mbarrier.init.shared.b64 [%0], 1;" :: "r"(mbar) : "memory");
}
__inline__ __device__ void mbar_expect_tx(unsigned mbar, unsigned bytes) {
    asm volatile("mbarrier.arrive.expect_tx.shared.b64 _, [%0], %1;"
                 :: "r"(mbar), "r"(bytes) : "memory");
}
__inline__ __device__ void bulk_g2s(unsigned dst, const void* src, unsigned bytes,
                                    unsigned mbar) {
    asm volatile(
        "cp.async.bulk.shared::cta.global.mbarrier::complete_tx::bytes [%0], [%1], %2, [%3];"
        :: "r"(dst), "l"(src), "r"(bytes), "r"(mbar) : "memory");
}
__inline__ __device__ void mbar_wait0(unsigned mbar) {
    asm volatile(
        "{\n\t"
        ".reg .pred P1;\n\t"
        "WAIT_LOOP_%=:\n\t"
        "mbarrier.try_wait.parity.acquire.cta.shared::cta.b64 P1, [%0], 0, 0x989680;\n\t"
        "@P1 bra.uni WAIT_DONE_%=;\n\t"
        "bra.uni WAIT_LOOP_%=;\n\t"
        "WAIT_DONE_%=:\n\t"
        "}"
        :: "r"(mbar) : "memory");
}

// ---------------- K1: fused attn_logits + gh0 + gh1 -------------------------
__global__ void __launch_bounds__(256) k_phase1(
        const long long* __restrict__ ids,
        const float* __restrict__ emb,
        const float* __restrict__ hidden,
        const float* __restrict__ attn_w,
        const float* __restrict__ attn_b,
        const float* __restrict__ w_hh0,
        const float* __restrict__ b_hh0,
        const float* __restrict__ w_hh1,
        const float* __restrict__ b_hh1) {
    __shared__ alignas(128) float4 sw[2048];   // 32KB
    __shared__ alignas(8) unsigned long long mbar_s;
    __shared__ float shpart[8];
    int t = threadIdx.x, warp = t >> 5, lane = t & 31;
    unsigned mbar = (unsigned)__cvta_generic_to_shared(&mbar_s);
    unsigned sdst = (unsigned)__cvta_generic_to_shared(sw);
    int b = blockIdx.x;

    if (t == 0) mbar_init(mbar);
    __syncthreads();

    if (b < 32) {
        int row0 = b * 4;  // 4 rows of width 2048
        if (t == 0) {
            mbar_expect_tx(mbar, 32768);
            bulk_g2s(sdst, attn_w + (size_t)row0 * (2 * H), 32768, mbar);
        }
        const float4* src = (warp & 1) ? (const float4*)hidden
                                       : (const float4*)(emb + (size_t)ids[0] * H);
        float4 xv[8];
        #pragma unroll
        for (int i = 0; i < 8; i++) xv[i] = __ldg(&src[lane + 32 * i]);
        mbar_wait0(mbar);
        float s = 0.f;
        #pragma unroll
        for (int i = 0; i < 8; i++) s += dot4(sw[warp * 256 + lane + 32 * i], xv[i]);
        s = warpReduceSum(s);
        if (lane == 0) shpart[warp] = s;
        __syncthreads();
        if (t < 4) g_attn_logits[row0 + t] = shpart[2 * t] + shpart[2 * t + 1] + attn_b[row0 + t];
    } else {
        bool is0 = (b < 32 + 384);
        int row0 = (is0 ? (b - 32) : (b - 416)) * 8;
        const float* wmat = is0 ? w_hh0 : w_hh1;
        const float* bias = is0 ? b_hh0 : b_hh1;
        const float4* hv4 = (const float4*)(is0 ? hidden : hidden + H);
        float* dst = is0 ? g_gh0 : g_gh1;
        if (t == 0) {
            mbar_expect_tx(mbar, 32768);
            bulk_g2s(sdst, wmat + (size_t)row0 * H, 32768, mbar);
        }
        float4 xv[8];
        #pragma unroll
        for (int i = 0; i < 8; i++) xv[i] = __ldg(&hv4[lane + 32 * i]);
        mbar_wait0(mbar);
        float s = 0.f;
        #pragma unroll
        for (int i = 0; i < 8; i++) s += dot4(sw[warp * 256 + lane + 32 * i], xv[i]);
        s = warpReduceSum(s);
        int row = row0 + warp;
        if (lane == 0) dst[row] = s + bias[row];
    }
    trigger_done();
}

// ---------------- K2: softmax (redundant per block) + attn_applied ----------
__global__ void k_softmax_applied(const float* __restrict__ enc,
                                  float* __restrict__ out) {
    cudaGridDependencySynchronize();
    __shared__ float sh[32];
    __shared__ float sM, sS;
    __shared__ float aw[L];
    int t = threadIdx.x;  // 128
    float v = g_attn_logits[t];
    float m = blockReduceMax(v, sh);
    if (t == 0) sM = m;
    __syncthreads();
    float e = expf(v - sM);
    __syncthreads();
    float s = blockReduceSum(e, sh);
    if (t == 0) sS = s;
    __syncthreads();
    float w = e / sS;
    aw[t] = w;
    if (blockIdx.x == 0) out[V + 2 * H + t] = w;
    __syncthreads();
    int h = blockIdx.x * 128 + t;
    float acc = 0.f;
    #pragma unroll 8
    for (int l = 0; l < L; l++) acc += aw[l] * enc[(size_t)l * H + h];
    g_attn_applied[h] = acc;
    trigger_done();
}

// ---------------- K3: comb + relu (4 rows x 2048 per block) ------------------
__global__ void __launch_bounds__(256) k_comb(
        const long long* __restrict__ ids,
        const float* __restrict__ emb,
        const float* __restrict__ comb_w,
        const float* __restrict__ comb_b) {
    __shared__ alignas(128) float4 sw[2048];
    __shared__ alignas(8) unsigned long long mbar_s;
    __shared__ float shpart[8];
    int t = threadIdx.x, warp = t >> 5, lane = t & 31;
    unsigned mbar = (unsigned)__cvta_generic_to_shared(&mbar_s);
    unsigned sdst = (unsigned)__cvta_generic_to_shared(sw);
    int row0 = blockIdx.x * 4;

    if (t == 0) mbar_init(mbar);
    __syncthreads();
    if (t == 0) {
        mbar_expect_tx(mbar, 32768);
        bulk_g2s(sdst, comb_w + (size_t)row0 * (2 * H), 32768, mbar);  // weights: no dep
    }
    cudaGridDependencySynchronize();   // wait for attn_applied
    const float4* src = (warp & 1) ? (const float4*)g_attn_applied
                                   : (const float4*)(emb + (size_t)ids[0] * H);
    float4 xv[8];
    #pragma unroll
    for (int i = 0; i < 8; i++) xv[i] = __ldg(&src[lane + 32 * i]);
    mbar_wait0(mbar);
    float s = 0.f;
    #pragma unroll
    for (int i = 0; i < 8; i++) s += dot4(sw[warp * 256 + lane + 32 * i], xv[i]);
    s = warpReduceSum(s);
    if (lane == 0) shpart[warp] = s;
    __syncthreads();
    if (t < 4) {
        float r = shpart[2 * t] + shpart[2 * t + 1] + comb_b[row0 + t];
        g_x[row0 + t] = r > 0.f ? r : 0.f;
    }
    trigger_done();
}

// ---------------- K4/K6: gi = x @ w_ih^T + b_ih (8 rows x 1024) --------------
__global__ void __launch_bounds__(256) k_gi(
        const float* __restrict__ xin,
        const float* __restrict__ w_ih,
        const float* __restrict__ b_ih,
        float* __restrict__ gi) {
    __shared__ alignas(128) float4 sw[2048];
    __shared__ alignas(8) unsigned long long mbar_s;
    int t = threadIdx.x, warp = t >> 5, lane = t & 31;
    unsigned mbar = (unsigned)__cvta_generic_to_shared(&mbar_s);
    unsigned sdst = (unsigned)__cvta_generic_to_shared(sw);
    int row0 = blockIdx.x * 8;

    if (t == 0) mbar_init(mbar);
    __syncthreads();
    if (t == 0) {
        mbar_expect_tx(mbar, 32768);
        bulk_g2s(sdst, w_ih + (size_t)row0 * H, 32768, mbar);   // weights: no dep
    }
    cudaGridDependencySynchronize();   // wait for x / h0
    const float4* x4 = (const float4*)xin;
    float4 xv[8];
    #pragma unroll
    for (int i = 0; i < 8; i++) xv[i] = __ldg(&x4[lane + 32 * i]);
    mbar_wait0(mbar);
    float s = 0.f;
    #pragma unroll
    for (int i = 0; i < 8; i++) s += dot4(sw[warp * 256 + lane + 32 * i], xv[i]);
    s = warpReduceSum(s);
    int row = row0 + warp;
    if (lane == 0) gi[row] = s + b_ih[row];
    trigger_done();
}

// ---------------- K5/K7: GRU combine ------------------------------------------
__global__ void k_combine(const float* __restrict__ gi,
                          const float* __restrict__ gh,
                          const float* __restrict__ hprev,
                          float* __restrict__ hnew,
                          float* __restrict__ out_hid) {
    cudaGridDependencySynchronize();
    int t = threadIdx.x;
    float r = 1.f / (1.f + expf(-(gi[t] + gh[t])));
    float z = 1.f / (1.f + expf(-(gi[H + t] + gh[H + t])));
    float n = tanhf(gi[2 * H + t] + r * gh[2 * H + t]);
    float h = (1.f - z) * n + z * hprev[t];
    hnew[t] = h;
    out_hid[t] = h;
    trigger_done();
}

// ---------------- K8: logits (2 rows/warp; weights loaded pre-sync) ----------
__global__ void __launch_bounds__(256) k_logits(
        const float* __restrict__ out_w,
        const float* __restrict__ out_b,
        float* __restrict__ logits) {
    int warp = threadIdx.x >> 5;
    int lane = threadIdx.x & 31;
    int j0 = (blockIdx.x * 8 + warp) * 2;
    if (j0 >= V) { cudaGridDependencySynchronize(); return; }

    const float4* w0 = (const float4*)(out_w + (size_t)j0 * H);
    bool has1 = (j0 + 1) < V;
    const float4* w1 = (const float4*)(out_w + (size_t)(has1 ? j0 + 1 : j0) * H);

    // weight loads depend only on external input — start before the dependency sync
    float4 w0v[8], w1v[8];
    #pragma unroll
    for (int i = 0; i < 8; i++) w0v[i] = __ldcs(&w0[lane + 32 * i]);
    #pragma unroll
    for (int i = 0; i < 8; i++) w1v[i] = __ldcs(&w1[lane + 32 * i]);

    cudaGridDependencySynchronize();   // wait for h1

    const float4* h = (const float4*)g_h1;
    float4 hv[8];
    #pragma unroll
    for (int i = 0; i < 8; i++) hv[i] = __ldg(&h[lane + 32 * i]);

    float s0 = 0.f, s1 = 0.f;
    #pragma unroll
    for (int i = 0; i < 8; i++) {
        s0 += dot4(w0v[i], hv[i]);
        s1 += dot4(w1v[i], hv[i]);
    }
    s0 = warpReduceSum(s0);
    s1 = warpReduceSum(s1);
    if (lane == 0) {
        logits[j0] = s0 + out_b[j0];
        if (has1) logits[j0 + 1] = s1 + out_b[j0 + 1];
    }
    cudaTriggerProgrammaticLaunchCompletion();
}

// ---------------- K9: fused LSE (partials + grid sync + apply) ----------------
// 128 blocks = single wave on 148 SMs => co-resident, flag sync is deadlock-free.
__global__ void __launch_bounds__(256) k_lse(float* __restrict__ logits) {
    __shared__ float sh[32];
    __shared__ float sM;
    __shared__ unsigned sE0;
    int t = threadIdx.x;

    // snapshot epoch before contributing (all prior-run state quiescent at entry)
    if (t == 0) sE0 = *((volatile unsigned*)&g_lse_epoch);

    cudaGridDependencySynchronize();   // wait for logits

    const int chunk = (V + RED_BLOCKS - 1) / RED_BLOCKS;  // 393
    int start = blockIdx.x * chunk;
    int end = min(start + chunk, V);
    float m = -INFINITY;
    for (int i = start + t; i < end; i += blockDim.x)
        m = fmaxf(m, logits[i]);
    m = blockReduceMax(m, sh);
    if (t == 0) sM = m;
    __syncthreads();
    float M = sM;
    float s = 0.f;
    for (int i = start + t; i < end; i += blockDim.x)
        s += expf(logits[i] - M);
    __syncthreads();
    s = blockReduceSum(s, sh);

    if (t == 0) {
        g_red_max[blockIdx.x] = M;
        g_red_sum[blockIdx.x] = s;
        __threadfence();                       // release partials
        unsigned old = atomicAdd(&g_lse_ctr, 1u);
        if (old == RED_BLOCKS - 1) {
            g_lse_ctr = 0;                     // all adds done; safe reset
            __threadfence();
            atomicAdd(&g_lse_epoch, 1u);       // signal: all partials visible
        }
        // spin until epoch advances past snapshot
        unsigned e;
        do {
            asm volatile("ld.acquire.gpu.u32 %0, [%1];" : "=r"(e) : "l"(&g_lse_epoch));
            if (e == sE0) __nanosleep(32);
        } while (e == sE0);
    }
    __syncthreads();

    // every block redundantly reduces the 128 partials (L2-hot)
    float pm = (t < RED_BLOCKS) ? g_red_max[t] : -INFINITY;
    float PM = blockReduceMax(pm, sh);
    if (t == 0) sM = PM;
    __syncthreads();
    PM = sM;
    float ps = (t < RED_BLOCKS) ? g_red_sum[t] * expf(g_red_max[t] - PM) : 0.f;
    __syncthreads();
    ps = blockReduceSum(ps, sh);
    __shared__ float sLogZ;
    if (t == 0) sLogZ = PM + logf(ps);
    __syncthreads();
    float lz = sLogZ;

    for (int i = start + t; i < end; i += blockDim.x)
        logits[i] -= lz;
}

// =================================================================================
template <typename... Args>
static void launch_pdl(void (*kern)(Args...), dim3 grid, dim3 block, Args... args) {
    cudaLaunchConfig_t cfg = {};
    cfg.gridDim = grid;
    cfg.blockDim = block;
    cfg.dynamicSmemBytes = 0;
    cfg.stream = 0;
    cudaLaunchAttribute attr[1];
    attr[0].id = cudaLaunchAttributeProgrammaticStreamSerialization;
    attr[0].val.programmaticStreamSerializationAllowed = 1;
    cfg.attrs = attr;
    cfg.numAttrs = 1;
    cudaLaunchKernelEx(&cfg, kern, args...);
}

extern "C" void kernel_launch(void* const* d_in, const int* in_sizes, int n_in,
                              void* d_out, int out_size) {
    const long long* input_ids = (const long long*)d_in[0];
    const float* hidden  = (const float*)d_in[1];
    const float* enc     = (const float*)d_in[2];
    const float* emb     = (const float*)d_in[3];
    const float* attn_w  = (const float*)d_in[4];
    const float* attn_b  = (const float*)d_in[5];
    const float* comb_w  = (const float*)d_in[6];
    const float* comb_b  = (const float*)d_in[7];
    const float* w_ih0   = (const float*)d_in[8];
    const float* w_hh0   = (const float*)d_in[9];
    const float* b_ih0   = (const float*)d_in[10];
    const float* b_hh0   = (const float*)d_in[11];
    const float* w_ih1   = (const float*)d_in[12];
    const float* w_hh1   = (const float*)d_in[13];
    const float* b_ih1   = (const float*)d_in[14];
    const float* b_hh1   = (const float*)d_in[15];
    const float* out_w   = (const float*)d_in[16];
    const float* out_b   = (const float*)d_in[17];

    float* out = (float*)d_out;

    const float* h0_prev = hidden;
    const float* h1_prev = hidden + H;

    float* p_x;   cudaGetSymbolAddress((void**)&p_x, g_x);
    float* p_h0;  cudaGetSymbolAddress((void**)&p_h0, g_h0);
    float* p_h1;  cudaGetSymbolAddress((void**)&p_h1, g_h1);
    float* p_gi0; cudaGetSymbolAddress((void**)&p_gi0, g_gi0);
    float* p_gh0; cudaGetSymbolAddress((void**)&p_gh0, g_gh0);
    float* p_gi1; cudaGetSymbolAddress((void**)&p_gi1, g_gi1);
    float* p_gh1; cudaGetSymbolAddress((void**)&p_gh1, g_gh1);

    // Phase 1 (first node: plain launch)
    k_phase1<<<32 + 2 * 384, 256>>>(input_ids, emb, hidden, attn_w, attn_b,
                                    w_hh0, b_hh0, w_hh1, b_hh1);
    // All successors: PDL — launch early; predecessors trigger only after writes
    launch_pdl(k_softmax_applied, dim3(8), dim3(128), enc, out);
    launch_pdl(k_comb, dim3(H / 4), dim3(256), input_ids, emb, comb_w, comb_b);
    launch_pdl(k_gi, dim3(3 * H / 8), dim3(256),
               (const float*)p_x, w_ih0, b_ih0, p_gi0);
    launch_pdl(k_combine, dim3(1), dim3(H),
               (const float*)p_gi0, (const float*)p_gh0, h0_prev, p_h0, out + V);
    launch_pdl(k_gi, dim3(3 * H / 8), dim3(256),
               (const float*)p_h0, w_ih1, b_ih1, p_gi1);
    launch_pdl(k_combine, dim3(1), dim3(H),
               (const float*)p_gi1, (const float*)p_gh1, h1_prev, p_h1, out + V + H);
    launch_pdl(k_logits, dim3((V + 15) / 16), dim3(256), out_w, out_b, out);
    launch_pdl(k_lse, dim3(RED_BLOCKS), dim3(256), out);
}